// round 1
// baseline (speedup 1.0000x reference)
#include <cuda_runtime.h>

// FP_14396730376440 — fan-beam forward projection
// sino[d,v] = sum_s weighting[d,v,s] * bilinear(img, grid_pos[d,v,s,:])
//
// Shapes: img [1,1,256,256] f32, grid_pos [368,180,513,2] f32,
//         weighting [1,1,368,180,513] f32, out [1,1,368,180] f32.

#define ND 368
#define NV 180
#define NS 513
#define NRAYS (ND * NV)
#define IMG_W 256
#define IMG_H 256
#define WARPS_PER_BLOCK 8

__global__ __launch_bounds__(WARPS_PER_BLOCK * 32)
void fp_kernel(const float* __restrict__ img,
               const float2* __restrict__ gp,
               const float* __restrict__ wt,
               float* __restrict__ out)
{
    const int lane = threadIdx.x & 31;
    const int warp = threadIdx.x >> 5;
    const int ray  = blockIdx.x * WARPS_PER_BLOCK + warp;
    if (ray >= NRAYS) return;

    const long long base = (long long)ray * NS;
    const float* wrow  = wt + base;
    const float2* grow = gp + base;

    float acc = 0.0f;

    const int n_iter = (NS + 31) / 32;  // 17
    for (int it = 0; it < n_iter; ++it) {
        const int s = it * 32 + lane;
        float w = 0.0f;
        if (s < NS) w = wrow[s];

        // Zeros in weighting form a contiguous suffix per ray (NaNs sort last
        // in the reference, diffs past the valid prefix are nan_to_num'ed to 0).
        // If the whole warp sees zero, everything after is zero too.
        const unsigned alive = __ballot_sync(0xffffffffu, w != 0.0f);
        if (alive == 0u) break;

        if (w != 0.0f) {
            const float2 g = grow[s];
            // ix = ((gx+1)*W - 1)*0.5 = gx*128 + 127.5  (W = H = 256)
            const float ix = fmaf(g.x, 128.0f, 127.5f);
            const float iy = fmaf(g.y, 128.0f, 127.5f);
            const float x0f = floorf(ix);
            const float y0f = floorf(iy);
            const int x0 = (int)x0f;
            const int y0 = (int)y0f;
            const float fx = ix - x0f;
            const float fy = iy - y0f;

            const bool vx0 = ((unsigned)x0       < (unsigned)IMG_W);
            const bool vx1 = ((unsigned)(x0 + 1) < (unsigned)IMG_W);
            const bool vy0 = ((unsigned)y0       < (unsigned)IMG_H);
            const bool vy1 = ((unsigned)(y0 + 1) < (unsigned)IMG_H);

            const int xi0 = vx0 ? x0     : 0;
            const int xi1 = vx1 ? x0 + 1 : 0;
            const int yi0 = vy0 ? y0     : 0;
            const int yi1 = vy1 ? y0 + 1 : 0;

            const float v00 = (vx0 && vy0) ? __ldg(img + yi0 * IMG_W + xi0) : 0.0f;
            const float v10 = (vx1 && vy0) ? __ldg(img + yi0 * IMG_W + xi1) : 0.0f;
            const float v01 = (vx0 && vy1) ? __ldg(img + yi1 * IMG_W + xi0) : 0.0f;
            const float v11 = (vx1 && vy1) ? __ldg(img + yi1 * IMG_W + xi1) : 0.0f;

            // Match reference: sum of 4 weighted corners
            const float s00 = (1.0f - fx) * (1.0f - fy);
            const float s10 = fx * (1.0f - fy);
            const float s01 = (1.0f - fx) * fy;
            const float s11 = fx * fy;
            const float samp = v00 * s00 + v10 * s10 + v01 * s01 + v11 * s11;

            acc = fmaf(w, samp, acc);
        }
    }

    // Warp reduction
    #pragma unroll
    for (int off = 16; off > 0; off >>= 1)
        acc += __shfl_down_sync(0xffffffffu, acc, off);

    if (lane == 0) out[ray] = acc;
}

extern "C" void kernel_launch(void* const* d_in, const int* in_sizes, int n_in,
                              void* d_out, int out_size)
{
    const float*  img = (const float*)d_in[0];
    const float2* gp  = (const float2*)d_in[1];
    const float*  wt  = (const float*)d_in[2];
    float* out = (float*)d_out;

    const int blocks = (NRAYS + WARPS_PER_BLOCK - 1) / WARPS_PER_BLOCK;
    fp_kernel<<<blocks, WARPS_PER_BLOCK * 32>>>(img, gp, wt, out);
}

// round 2
// speedup vs baseline: 1.1336x; 1.1336x over previous
#include <cuda_runtime.h>

// FP_14396730376440 — fan-beam forward projection
// sino[d,v] = sum_s weighting[d,v,s] * bilinear(img, grid_pos[d,v,s,:])

#define ND 368
#define NV 180
#define NS 513
#define NRAYS (ND * NV)
#define IMG_W 256
#define IMG_H 256
#define PAD 2
#define PW (IMG_W + 2 * PAD)   // 260
#define WARPS_PER_BLOCK 8

// Zero-padded image: grid positions map to x0 in [-2,256] (a_mid is strictly
// inside the image square, |g| <= 128/127.5), so a 2-pixel zero border makes
// all 4 bilinear taps unconditional.
__device__ float d_img_pad[PW * PW];

__global__ void pad_img_kernel(const float* __restrict__ img)
{
    int idx = blockIdx.x * blockDim.x + threadIdx.x;
    if (idx >= PW * PW) return;
    int y = idx / PW, x = idx % PW;
    int iy = y - PAD, ix = x - PAD;
    float v = 0.0f;
    if ((unsigned)ix < (unsigned)IMG_W && (unsigned)iy < (unsigned)IMG_H)
        v = img[iy * IMG_W + ix];
    d_img_pad[idx] = v;
}

__device__ __forceinline__ float sample_bilinear(float2 g)
{
    // ix = ((gx+1)*256 - 1)*0.5 = gx*128 + 127.5
    const float ix = fmaf(g.x, 128.0f, 127.5f);
    const float iy = fmaf(g.y, 128.0f, 127.5f);
    const float x0f = floorf(ix);
    const float y0f = floorf(iy);
    const int x0 = (int)x0f;
    const int y0 = (int)y0f;
    const float fx = ix - x0f;
    const float fy = iy - y0f;

    const float* p = d_img_pad + (y0 + PAD) * PW + (x0 + PAD);
    const float v00 = __ldg(p);
    const float v10 = __ldg(p + 1);
    const float v01 = __ldg(p + PW);
    const float v11 = __ldg(p + PW + 1);

    const float t = fmaf(fx, v10 - v00, v00);
    const float b = fmaf(fx, v11 - v01, v01);
    return fmaf(fy, b - t, t);
}

__global__ __launch_bounds__(WARPS_PER_BLOCK * 32)
void fp_kernel(const float2* __restrict__ gp,
               const float* __restrict__ wt,
               float* __restrict__ out)
{
    const int lane = threadIdx.x & 31;
    const int warp = threadIdx.x >> 5;
    const int ray  = blockIdx.x * WARPS_PER_BLOCK + warp;
    if (ray >= NRAYS) return;

    const long long base = (long long)ray * NS;
    const float*  wrow = wt + base;
    const float2* grow = gp + base;

    float acc = 0.0f;

    // Tail sample s = 512 (lane 0 only) — folded in up front.
    if (lane == 0) {
        const float w = wrow[NS - 1];
        if (w != 0.0f) acc = w * sample_bilinear(grow[NS - 1]);
    }

    // 8 iterations x 64 samples = 512. Zeros in weighting form a contiguous
    // suffix per ray (NaNs sort last in the reference; diffs past the valid
    // prefix are nan_to_num'ed to 0), so an all-zero 64-block ends the ray.
    for (int it = 0; it < 8; ++it) {
        const int s0 = it * 64 + lane;
        const int s1 = s0 + 32;
        const float w0 = wrow[s0];
        const float w1 = wrow[s1];

        const unsigned alive =
            __ballot_sync(0xffffffffu, (w0 != 0.0f) || (w1 != 0.0f));
        if (alive == 0u) break;

        if (w0 != 0.0f) {
            const float2 g0 = grow[s0];
            acc = fmaf(w0, sample_bilinear(g0), acc);
        }
        if (w1 != 0.0f) {
            const float2 g1 = grow[s1];
            acc = fmaf(w1, sample_bilinear(g1), acc);
        }
    }

    #pragma unroll
    for (int off = 16; off > 0; off >>= 1)
        acc += __shfl_down_sync(0xffffffffu, acc, off);

    if (lane == 0) out[ray] = acc;
}

extern "C" void kernel_launch(void* const* d_in, const int* in_sizes, int n_in,
                              void* d_out, int out_size)
{
    const float*  img = (const float*)d_in[0];
    const float2* gp  = (const float2*)d_in[1];
    const float*  wt  = (const float*)d_in[2];
    float* out = (float*)d_out;

    pad_img_kernel<<<(PW * PW + 255) / 256, 256>>>(img);

    const int blocks = (NRAYS + WARPS_PER_BLOCK - 1) / WARPS_PER_BLOCK;
    fp_kernel<<<blocks, WARPS_PER_BLOCK * 32>>>(gp, wt, out);
}

// round 3
// speedup vs baseline: 1.5643x; 1.3800x over previous
#include <cuda_runtime.h>

// FP_14396730376440 — fan-beam forward projection
// sino[d,v] = sum_s weighting[d,v,s] * bilinear(img, grid_pos[d,v,s,:])

#define ND 368
#define NV 180
#define NS 513
#define NRAYS (ND * NV)
#define IMG_W 256
#define IMG_H 256
#define PAD 2
#define PW (IMG_W + 2 * PAD)   // 260
#define WARPS_PER_BLOCK 8

// Pair-packed zero-padded image: d_img_pair[y*PW+x] = (pad(y,x), pad(y,x+1)).
// Valid grid positions map ix,iy into [-1, 256]; with PAD=2 all taps are in
// bounds and 8-byte aligned. One float2 load yields both x-neighbors.
__device__ float2 d_img_pair[PW * PW];

__global__ void pad_img_kernel(const float* __restrict__ img)
{
    int idx = blockIdx.x * blockDim.x + threadIdx.x;
    if (idx >= PW * PW) return;
    int y = idx / PW, x = idx % PW;
    int iy = y - PAD;
    auto px = [&](int xx) -> float {
        int ix = xx - PAD;
        if ((unsigned)ix < (unsigned)IMG_W && (unsigned)iy < (unsigned)IMG_H)
            return img[iy * IMG_W + ix];
        return 0.0f;
    };
    d_img_pair[idx] = make_float2(px(x), px(x + 1));
}

__device__ __forceinline__ float sample_bilinear(float2 g)
{
    // ix = ((gx+1)*256 - 1)*0.5 = gx*128 + 127.5; valid range [-1, 256].
    // Clamp so w==0 lanes (whose g encodes the source point, far outside)
    // still read in-bounds; their contribution is multiplied by w=0.
    float ix = fmaf(g.x, 128.0f, 127.5f);
    float iy = fmaf(g.y, 128.0f, 127.5f);
    ix = fminf(fmaxf(ix, -1.0f), 256.0f);
    iy = fminf(fmaxf(iy, -1.0f), 256.0f);
    const float x0f = floorf(ix);
    const float y0f = floorf(iy);
    const int x0 = (int)x0f;
    const int y0 = (int)y0f;
    const float fx = ix - x0f;
    const float fy = iy - y0f;

    const float2* p = d_img_pair + (y0 + PAD) * PW + (x0 + PAD);
    const float2 t0 = __ldg(p);        // v00, v10
    const float2 t1 = __ldg(p + PW);   // v01, v11

    const float top = fmaf(fx, t0.y - t0.x, t0.x);
    const float bot = fmaf(fx, t1.y - t1.x, t1.x);
    return fmaf(fy, bot - top, top);
}

__global__ __launch_bounds__(WARPS_PER_BLOCK * 32)
void fp_kernel(const float2* __restrict__ gp,
               const float* __restrict__ wt,
               float* __restrict__ out)
{
    const int lane = threadIdx.x & 31;
    const int warp = threadIdx.x >> 5;
    const int ray  = blockIdx.x * WARPS_PER_BLOCK + warp;
    if (ray >= NRAYS) return;

    const long long base = (long long)ray * NS;
    const float*  wrow = wt + base;
    const float2* grow = gp + base;

    float acc = 0.0f;

    // Tail sample s = 512 (lane 0 only).
    if (lane == 0) {
        const float w = wrow[NS - 1];
        if (w != 0.0f) acc = w * sample_bilinear(grow[NS - 1]);
    }

    // Software-pipelined: block it+1 loads issue before block it computes.
    float  w0 = wrow[lane];
    float  w1 = wrow[lane + 32];
    float2 g0 = grow[lane];
    float2 g1 = grow[lane + 32];

    for (int it = 0; it < 8; ++it) {
        // Zeros in weighting form a contiguous suffix per ray (NaNs sort to
        // the end in the reference), so an all-zero 64-block ends the ray.
        const unsigned alive =
            __ballot_sync(0xffffffffu, (w0 != 0.0f) || (w1 != 0.0f));
        if (alive == 0u) break;

        float  nw0 = 0.0f, nw1 = 0.0f;
        float2 ng0 = make_float2(0.f, 0.f), ng1 = ng0;
        if (it < 7) {
            const int s = (it + 1) * 64 + lane;
            nw0 = wrow[s];
            nw1 = wrow[s + 32];
            ng0 = grow[s];
            ng1 = grow[s + 32];
        }

        // Branch-free: fmaf(0, finite, acc) is exact for dead lanes.
        acc = fmaf(w0, sample_bilinear(g0), acc);
        acc = fmaf(w1, sample_bilinear(g1), acc);

        w0 = nw0; w1 = nw1; g0 = ng0; g1 = ng1;
    }

    #pragma unroll
    for (int off = 16; off > 0; off >>= 1)
        acc += __shfl_down_sync(0xffffffffu, acc, off);

    if (lane == 0) out[ray] = acc;
}

extern "C" void kernel_launch(void* const* d_in, const int* in_sizes, int n_in,
                              void* d_out, int out_size)
{
    const float*  img = (const float*)d_in[0];
    const float2* gp  = (const float2*)d_in[1];
    const float*  wt  = (const float*)d_in[2];
    float* out = (float*)d_out;

    pad_img_kernel<<<(PW * PW + 255) / 256, 256>>>(img);

    const int blocks = (NRAYS + WARPS_PER_BLOCK - 1) / WARPS_PER_BLOCK;
    fp_kernel<<<blocks, WARPS_PER_BLOCK * 32>>>(gp, wt, out);
}